// round 4
// baseline (speedup 1.0000x reference)
#include <cuda_runtime.h>
#include <cuda_bf16.h>
#include <math.h>

// Problem constants (fixed by the dataset)
#define NN 100000
#define NF 256
#define NH 16
#define NC 16
#define NE 3200000

#define SCAN_CHUNK 4096
#define SCAN_BLOCKS 25   // ceil(100000/4096)

#define GEMM_BLOCKS 782      // ceil(NN/128) nodes, 128 per block (2 nodes/thread)
#define SCATTER_BLOCKS 3125  // NE/4/256

typedef unsigned long long u64;

// ---------------- device scratch (static, allowed) ----------------
__device__ int   g_cnt[NN];            // in-degree (no self loop)
__device__ int   g_rowstart[NN + 1];   // CSR row offsets (by dst)
__device__ int   g_fill[NN];           // running fill cursor for scatter
__device__ int   g_blocksums[SCAN_BLOCKS];
__device__ float g_dinv[NN];           // rsqrt(indeg+1)
__device__ float g_h[NN * NH];         // (x@W1) * dinv[n]   (pre-scaled!)
__device__ float g_h1[NN * NH];        // GCN output
__device__ int   g_srcsorted[NE];      // src ids grouped by dst

// ---------------- f32x2 helpers (FFMA2 is PTX-only) ----------------
__device__ __forceinline__ u64 pk2(float a, float b) {
    u64 r; asm("mov.b64 %0, {%1, %2};" : "=l"(r) : "f"(a), "f"(b)); return r;
}
__device__ __forceinline__ u64 dup2(float a) {
    u64 r; asm("mov.b64 %0, {%1, %1};" : "=l"(r) : "f"(a)); return r;
}
__device__ __forceinline__ u64 ffma2(u64 a, u64 b, u64 c) {
    u64 d; asm("fma.rn.f32x2 %0, %1, %2, %3;" : "=l"(d) : "l"(a), "l"(b), "l"(c)); return d;
}
__device__ __forceinline__ float2 unpk2(u64 a) {
    float2 f; asm("mov.b64 {%0, %1}, %2;" : "=f"(f.x), "=f"(f.y) : "l"(a)); return f;
}

// ---------------- kernels ----------------

// histogram of dst (4 edges per thread via int4)
__global__ void k_count(const int* __restrict__ dst) {
    int i = blockIdx.x * blockDim.x + threadIdx.x;   // i < NE/4
    int4 d = ((const int4*)dst)[i];
    atomicAdd(&g_cnt[d.x], 1);
    atomicAdd(&g_cnt[d.y], 1);
    atomicAdd(&g_cnt[d.z], 1);
    atomicAdd(&g_cnt[d.w], 1);
}

// per-block exclusive scan of g_cnt chunk -> g_rowstart (local), block total -> g_blocksums
__global__ void k_scan_local() {
    __shared__ int s[SCAN_CHUNK];
    __shared__ int tsum[256];
    int t = threadIdx.x;
    int base = blockIdx.x * SCAN_CHUNK;
    for (int i = t; i < SCAN_CHUNK; i += 256) {
        int idx = base + i;
        s[i] = (idx < NN) ? g_cnt[idx] : 0;
    }
    __syncthreads();

    int loc[16];
    int run = 0;
#pragma unroll
    for (int i = 0; i < 16; i++) {
        run += s[t * 16 + i];
        loc[i] = run;                 // inclusive within thread
    }
    tsum[t] = run;
    __syncthreads();
    for (int off = 1; off < 256; off <<= 1) {
        int v = (t >= off) ? tsum[t - off] : 0;
        __syncthreads();
        tsum[t] += v;
        __syncthreads();
    }
    int ex = (t == 0) ? 0 : tsum[t - 1];
#pragma unroll
    for (int i = 0; i < 16; i++) {
        s[t * 16 + i] = ex + (i ? loc[i - 1] : 0);   // exclusive per element
    }
    __syncthreads();
    for (int i = t; i < SCAN_CHUNK; i += 256) {
        int idx = base + i;
        if (idx < NN) g_rowstart[idx] = s[i];
    }
    if (t == 0) g_blocksums[blockIdx.x] = tsum[255];
}

// fixup: add scanned block sums (computed in smem here), init fill/dinv
__global__ void k_fixup() {
    __shared__ int sbs[SCAN_BLOCKS];
    int t = threadIdx.x;
    if (t < SCAN_BLOCKS) sbs[t] = g_blocksums[t];
    __syncthreads();
    int i = blockIdx.x * 256 + t;
    if (i >= NN) return;
    int chunk = i >> 12;          // / SCAN_CHUNK
    int off = 0;
    for (int b = 0; b < chunk; b++) off += sbs[b];
    int r = g_rowstart[i] + off;
    g_rowstart[i] = r;
    g_fill[i] = r;
    g_dinv[i] = rsqrtf((float)(g_cnt[i] + 1));
    if (i == 0) g_rowstart[NN] = NE;
}

// ---- fused scatter + gemm1 ----
// blocks [0, GEMM_BLOCKS): g_h[n,:] = (x[n,:] @ W1) * dinv[n]  (DRAM-bound, 2 nodes/thread)
// blocks [GEMM_BLOCKS, ...): CSR scatter (L2/atomic-latency bound)
// launch_bounds(256,5) keeps regs <=51 so scatter blocks keep >=62% occupancy.
__global__ void __launch_bounds__(256, 5)
k_scatter_gemm(const int* __restrict__ src, const int* __restrict__ dst,
               const float* __restrict__ x, const float* __restrict__ W1) {
    __shared__ float sW[NF * NH];   // 16 KB (unused by scatter blocks)
    int t = threadIdx.x;

    if (blockIdx.x >= GEMM_BLOCKS) {
        // ---------------- scatter path ----------------
        int i = (blockIdx.x - GEMM_BLOCKS) * 256 + t;   // i < NE/4
        int4 s = ((const int4*)src)[i];
        int4 d = ((const int4*)dst)[i];
        int p0 = atomicAdd(&g_fill[d.x], 1);
        int p1 = atomicAdd(&g_fill[d.y], 1);
        int p2 = atomicAdd(&g_fill[d.z], 1);
        int p3 = atomicAdd(&g_fill[d.w], 1);
        g_srcsorted[p0] = s.x;
        g_srcsorted[p1] = s.y;
        g_srcsorted[p2] = s.z;
        g_srcsorted[p3] = s.w;
        return;
    }

    // ---------------- gemm path (2 nodes/thread) ----------------
    for (int i = t; i < NF * NH; i += 256) sW[i] = W1[i];
    __syncthreads();

    int q = t & 3;
    int slot = t >> 2;                 // 0..63
    int base = blockIdx.x * 128;
    int n0 = base + slot;
    int n1 = n0 + 64;
    int c0 = min(n0, NN - 1), c1 = min(n1, NN - 1);

    const float4* x0 = (const float4*)(x + (size_t)c0 * NF);
    const float4* x1 = (const float4*)(x + (size_t)c1 * NF);
    const float4* w4 = (const float4*)sW;   // w4[k*4 + q] = W1[k][4q..4q+3]

    u64 a00 = 0, a01 = 0, a10 = 0, a11 = 0;

#define NODE_STEP(V, A0, A1)                                        \
    do {                                                            \
        u64 dx = dup2((V).x), dy = dup2((V).y);                     \
        u64 dz = dup2((V).z), dw = dup2((V).w);                     \
        A0 = ffma2(dx, w0a, A0); A1 = ffma2(dx, w0b, A1);           \
        A0 = ffma2(dy, w1a, A0); A1 = ffma2(dy, w1b, A1);           \
        A0 = ffma2(dz, w2a, A0); A1 = ffma2(dz, w2b, A1);           \
        A0 = ffma2(dw, w3a, A0); A1 = ffma2(dw, w3b, A1);           \
    } while (0)

#pragma unroll 4
    for (int kk = 0; kk < 64; kk++) {
        float4 v0 = __ldg(&x0[kk]);
        float4 v1 = __ldg(&x1[kk]);
        int kb = kk * 16 + q;
        float4 w0 = w4[kb];
        float4 w1 = w4[kb + 4];
        float4 w2 = w4[kb + 8];
        float4 w3 = w4[kb + 12];
        u64 w0a = pk2(w0.x, w0.y), w0b = pk2(w0.z, w0.w);
        u64 w1a = pk2(w1.x, w1.y), w1b = pk2(w1.z, w1.w);
        u64 w2a = pk2(w2.x, w2.y), w2b = pk2(w2.z, w2.w);
        u64 w3a = pk2(w3.x, w3.y), w3b = pk2(w3.z, w3.w);
        NODE_STEP(v0, a00, a01);
        NODE_STEP(v1, a10, a11);
    }
#undef NODE_STEP

    {
        int ns[2] = {n0, n1};
        u64 lo[2] = {a00, a10};
        u64 hi[2] = {a01, a11};
#pragma unroll
        for (int j = 0; j < 2; j++) {
            int n = ns[j];
            if (n < NN) {
                float dv = g_dinv[n];
                float2 l = unpk2(lo[j]), h = unpk2(hi[j]);
                float4 r = make_float4(l.x * dv, l.y * dv, h.x * dv, h.y * dv);
                *(float4*)&g_h[n * NH + q * 4] = r;
            }
        }
    }
}

// GCN aggregate: h1[n] = dinv[n] * (sum_{in-edges} g_h[src] + g_h[n]) + b1
// one warp per node; 8 edge-slots x 4 lanes (each lane handles a c-quad)
__global__ void k_gcn(const float* __restrict__ b1) {
    int gw = (blockIdx.x * blockDim.x + threadIdx.x) >> 5;
    int lane = threadIdx.x & 31;
    if (gw >= NN) return;
    int n = gw;
    int start = g_rowstart[n];
    int end   = g_rowstart[n + 1];
    int grp = lane >> 2, q = lane & 3;

    float4 acc = make_float4(0.f, 0.f, 0.f, 0.f);
    for (int j = start + grp; j < end; j += 8) {
        int s = __ldg(&g_srcsorted[j]);
        float4 v = __ldg((const float4*)&g_h[s * NH + q * 4]);
        acc.x += v.x; acc.y += v.y; acc.z += v.z; acc.w += v.w;
    }
#pragma unroll
    for (int d = 4; d < 32; d <<= 1) {
        acc.x += __shfl_xor_sync(0xffffffffu, acc.x, d);
        acc.y += __shfl_xor_sync(0xffffffffu, acc.y, d);
        acc.z += __shfl_xor_sync(0xffffffffu, acc.z, d);
        acc.w += __shfl_xor_sync(0xffffffffu, acc.w, d);
    }
    if (lane < 4) {
        float4 self = *(const float4*)&g_h[n * NH + lane * 4];
        float dv = g_dinv[n];
        float4 bb = __ldg((const float4*)&b1[lane * 4]);
        float4 r;
        r.x = (acc.x + self.x) * dv + bb.x;
        r.y = (acc.y + self.y) * dv + bb.y;
        r.z = (acc.z + self.z) * dv + bb.z;
        r.w = (acc.w + self.w) * dv + bb.w;
        *(float4*)&g_h1[n * NH + lane * 4] = r;
    }
}

// SAGE: agg = mean_{in-edges} h1[src]; out = agg@Wl + h1[n]@Wr + b2; log_softmax
__global__ void k_sage(const float* __restrict__ Wl, const float* __restrict__ Wr,
                       const float* __restrict__ b2, float* __restrict__ out) {
    __shared__ float sWl[NH * NC], sWr[NH * NC], sB2[NC];
    __shared__ float sAgg[8][16], sH1[8][16];
    int t = threadIdx.x;
    for (int i = t; i < NH * NC; i += 256) { sWl[i] = Wl[i]; sWr[i] = Wr[i]; }
    if (t < NC) sB2[t] = b2[t];
    __syncthreads();

    int wib = t >> 5, lane = t & 31;
    int n = blockIdx.x * 8 + wib;
    if (n >= NN) return;

    int start = g_rowstart[n];
    int end   = g_rowstart[n + 1];
    int grp = lane >> 2, q = lane & 3;

    float4 acc = make_float4(0.f, 0.f, 0.f, 0.f);
    for (int j = start + grp; j < end; j += 8) {
        int s = __ldg(&g_srcsorted[j]);
        float4 v = __ldg((const float4*)&g_h1[s * NH + q * 4]);
        acc.x += v.x; acc.y += v.y; acc.z += v.z; acc.w += v.w;
    }
#pragma unroll
    for (int d = 4; d < 32; d <<= 1) {
        acc.x += __shfl_xor_sync(0xffffffffu, acc.x, d);
        acc.y += __shfl_xor_sync(0xffffffffu, acc.y, d);
        acc.z += __shfl_xor_sync(0xffffffffu, acc.z, d);
        acc.w += __shfl_xor_sync(0xffffffffu, acc.w, d);
    }
    float inv = 1.0f / fmaxf((float)(end - start), 1.0f);
    if (lane < 4) {
        float4 a;
        a.x = acc.x * inv; a.y = acc.y * inv; a.z = acc.z * inv; a.w = acc.w * inv;
        *(float4*)&sAgg[wib][lane * 4] = a;
        float4 h1v = *(const float4*)&g_h1[n * NH + lane * 4];
        *(float4*)&sH1[wib][lane * 4] = h1v;
    }
    __syncwarp();
    if (lane < 16) {
        float o = sB2[lane];
#pragma unroll
        for (int k = 0; k < 16; k++) {
            o += sAgg[wib][k] * sWl[k * NC + lane] + sH1[wib][k] * sWr[k * NC + lane];
        }
        float m = o;
#pragma unroll
        for (int d = 8; d >= 1; d >>= 1)
            m = fmaxf(m, __shfl_xor_sync(0xffffu, m, d));
        float e = __expf(o - m);
        float ssum = e;
#pragma unroll
        for (int d = 8; d >= 1; d >>= 1)
            ssum += __shfl_xor_sync(0xffffu, ssum, d);
        out[n * NC + lane] = (o - m) - __logf(ssum);
    }
}

// ---------------- launch ----------------
extern "C" void kernel_launch(void* const* d_in, const int* in_sizes, int n_in,
                              void* d_out, int out_size) {
    const float* x  = (const float*)d_in[0];
    const int*   ei = (const int*)d_in[1];
    const float* W1 = (const float*)d_in[2];
    const float* b1 = (const float*)d_in[3];
    const float* Wl = (const float*)d_in[4];
    const float* Wr = (const float*)d_in[5];
    const float* b2 = (const float*)d_in[6];
    float* out = (float*)d_out;

    const int* src = ei;
    const int* dst = ei + NE;

    void* cnt_ptr = nullptr;
    cudaGetSymbolAddress(&cnt_ptr, g_cnt);
    cudaMemsetAsync(cnt_ptr, 0, NN * sizeof(int), 0);

    k_count<<<(NE / 4) / 256, 256>>>(dst);
    k_scan_local<<<SCAN_BLOCKS, 256>>>();
    k_fixup<<<(NN + 255) / 256, 256>>>();
    k_scatter_gemm<<<GEMM_BLOCKS + SCATTER_BLOCKS, 256>>>(src, dst, x, W1);
    k_gcn<<<(NN * 32 + 255) / 256, 256>>>(b1);
    k_sage<<<(NN * 32 + 255) / 256, 256>>>(Wl, Wr, b2, out);
}

// round 5
// speedup vs baseline: 1.1666x; 1.1666x over previous
#include <cuda_runtime.h>
#include <cuda_bf16.h>
#include <math.h>

// Problem constants (fixed by the dataset)
#define NN 100000
#define NF 256
#define NH 16
#define NC 16
#define NE 3200000

#define SCAN_CHUNK 4096
#define SCAN_BLOCKS 25   // ceil(100000/4096)

#define GEMM_BLOCKS 391      // ceil(NN/256) nodes, 256/block (4 nodes/thread)
#define SCATTER_BLOCKS 3125  // NE/4/256

typedef unsigned long long u64;

// ---------------- device scratch (static, allowed) ----------------
__device__ int   g_cnt[NN];            // in-degree (no self loop)
__device__ int   g_rowstart[NN + 1];   // CSR row offsets (by dst)
__device__ int   g_blocksums[SCAN_BLOCKS];
__device__ float g_dinv[NN];           // rsqrt(indeg+1)
__device__ float g_h[NN * NH];         // (x@W1) * dinv[n]   (pre-scaled!)
__device__ float g_h1[NN * NH];        // GCN output
__device__ int   g_srcsorted[NE];      // src ids grouped by dst
__device__ int   g_rank[NE];           // per-edge rank within its dst bucket

// ---------------- f32x2 helpers (FFMA2 is PTX-only) ----------------
__device__ __forceinline__ u64 pk2(float a, float b) {
    u64 r; asm("mov.b64 %0, {%1, %2};" : "=l"(r) : "f"(a), "f"(b)); return r;
}
__device__ __forceinline__ u64 dup2(float a) {
    u64 r; asm("mov.b64 %0, {%1, %1};" : "=l"(r) : "f"(a)); return r;
}
__device__ __forceinline__ u64 ffma2(u64 a, u64 b, u64 c) {
    u64 d; asm("fma.rn.f32x2 %0, %1, %2, %3;" : "=l"(d) : "l"(a), "l"(b), "l"(c)); return d;
}
__device__ __forceinline__ float2 unpk2(u64 a) {
    float2 f; asm("mov.b64 {%0, %1}, %2;" : "=f"(f.x), "=f"(f.y) : "l"(a)); return f;
}

// ---------------- kernels ----------------

// histogram of dst + record each edge's rank within its bucket
__global__ void k_count(const int* __restrict__ dst) {
    int i = blockIdx.x * blockDim.x + threadIdx.x;   // i < NE/4
    int4 d = ((const int4*)dst)[i];
    int4 r;
    r.x = atomicAdd(&g_cnt[d.x], 1);
    r.y = atomicAdd(&g_cnt[d.y], 1);
    r.z = atomicAdd(&g_cnt[d.z], 1);
    r.w = atomicAdd(&g_cnt[d.w], 1);
    ((int4*)g_rank)[i] = r;
}

// per-block exclusive scan of g_cnt chunk -> g_rowstart (local), block total -> g_blocksums
__global__ void k_scan_local() {
    __shared__ int s[SCAN_CHUNK];
    __shared__ int tsum[256];
    int t = threadIdx.x;
    int base = blockIdx.x * SCAN_CHUNK;
    for (int i = t; i < SCAN_CHUNK; i += 256) {
        int idx = base + i;
        s[i] = (idx < NN) ? g_cnt[idx] : 0;
    }
    __syncthreads();

    int loc[16];
    int run = 0;
#pragma unroll
    for (int i = 0; i < 16; i++) {
        run += s[t * 16 + i];
        loc[i] = run;                 // inclusive within thread
    }
    tsum[t] = run;
    __syncthreads();
    for (int off = 1; off < 256; off <<= 1) {
        int v = (t >= off) ? tsum[t - off] : 0;
        __syncthreads();
        tsum[t] += v;
        __syncthreads();
    }
    int ex = (t == 0) ? 0 : tsum[t - 1];
#pragma unroll
    for (int i = 0; i < 16; i++) {
        s[t * 16 + i] = ex + (i ? loc[i - 1] : 0);   // exclusive per element
    }
    __syncthreads();
    for (int i = t; i < SCAN_CHUNK; i += 256) {
        int idx = base + i;
        if (idx < NN) g_rowstart[idx] = s[i];
    }
    if (t == 0) g_blocksums[blockIdx.x] = tsum[255];
}

// fixup: add scanned block sums (computed in smem here), init dinv
__global__ void k_fixup() {
    __shared__ int sbs[SCAN_BLOCKS];
    int t = threadIdx.x;
    if (t < SCAN_BLOCKS) sbs[t] = g_blocksums[t];
    __syncthreads();
    int i = blockIdx.x * 256 + t;
    if (i >= NN) return;
    int chunk = i >> 12;          // / SCAN_CHUNK
    int off = 0;
    for (int b = 0; b < chunk; b++) off += sbs[b];
    g_rowstart[i] += off;
    g_dinv[i] = rsqrtf((float)(g_cnt[i] + 1));
    if (i == 0) g_rowstart[NN] = NE;
}

// ---- fused scatter + gemm1 ----
// blocks [0, GEMM_BLOCKS): g_h[n,:] = (x[n,:] @ W1) * dinv[n]  (DRAM-bound, 4 nodes/thread)
// blocks [GEMM_BLOCKS, ...): atomic-free CSR scatter: pos = rowstart[dst] + rank
__global__ void __launch_bounds__(256)
k_scatter_gemm(const int* __restrict__ src, const int* __restrict__ dst,
               const float* __restrict__ x, const float* __restrict__ W1) {
    __shared__ float sW[NF * NH];   // 16 KB (unused by scatter blocks)
    int t = threadIdx.x;

    if (blockIdx.x >= GEMM_BLOCKS) {
        // ---------------- scatter path (no atomics) ----------------
        int i = (blockIdx.x - GEMM_BLOCKS) * 256 + t;   // i < NE/4
        int4 s = ((const int4*)src)[i];
        int4 d = ((const int4*)dst)[i];
        int4 r = ((const int4*)g_rank)[i];
        int p0 = __ldg(&g_rowstart[d.x]) + r.x;
        int p1 = __ldg(&g_rowstart[d.y]) + r.y;
        int p2 = __ldg(&g_rowstart[d.z]) + r.z;
        int p3 = __ldg(&g_rowstart[d.w]) + r.w;
        g_srcsorted[p0] = s.x;
        g_srcsorted[p1] = s.y;
        g_srcsorted[p2] = s.z;
        g_srcsorted[p3] = s.w;
        return;
    }

    // ---------------- gemm path (4 nodes/thread) ----------------
    for (int i = t; i < NF * NH; i += 256) sW[i] = W1[i];
    __syncthreads();

    int q = t & 3;
    int slot = t >> 2;                 // 0..63
    int base = blockIdx.x * 256;
    int n0 = base + slot;
    int n1 = n0 + 64, n2 = n0 + 128, n3 = n0 + 192;
    int c0 = min(n0, NN - 1), c1 = min(n1, NN - 1);
    int c2 = min(n2, NN - 1), c3 = min(n3, NN - 1);

    const float4* x0 = (const float4*)(x + (size_t)c0 * NF);
    const float4* x1 = (const float4*)(x + (size_t)c1 * NF);
    const float4* x2 = (const float4*)(x + (size_t)c2 * NF);
    const float4* x3 = (const float4*)(x + (size_t)c3 * NF);
    const float4* w4 = (const float4*)sW;   // w4[k*4 + q] = W1[k][4q..4q+3]

    u64 a00 = 0, a01 = 0, a10 = 0, a11 = 0, a20 = 0, a21 = 0, a30 = 0, a31 = 0;

#define NODE_STEP(V, A0, A1)                                        \
    do {                                                            \
        u64 dx = dup2((V).x), dy = dup2((V).y);                     \
        u64 dz = dup2((V).z), dw = dup2((V).w);                     \
        A0 = ffma2(dx, w0a, A0); A1 = ffma2(dx, w0b, A1);           \
        A0 = ffma2(dy, w1a, A0); A1 = ffma2(dy, w1b, A1);           \
        A0 = ffma2(dz, w2a, A0); A1 = ffma2(dz, w2b, A1);           \
        A0 = ffma2(dw, w3a, A0); A1 = ffma2(dw, w3b, A1);           \
    } while (0)

#pragma unroll 4
    for (int kk = 0; kk < 64; kk++) {
        float4 v0 = __ldcs(&x0[kk]);
        float4 v1 = __ldcs(&x1[kk]);
        float4 v2 = __ldcs(&x2[kk]);
        float4 v3 = __ldcs(&x3[kk]);
        int kb = kk * 16 + q;
        float4 w0 = w4[kb];
        float4 w1 = w4[kb + 4];
        float4 w2 = w4[kb + 8];
        float4 w3 = w4[kb + 12];
        u64 w0a = pk2(w0.x, w0.y), w0b = pk2(w0.z, w0.w);
        u64 w1a = pk2(w1.x, w1.y), w1b = pk2(w1.z, w1.w);
        u64 w2a = pk2(w2.x, w2.y), w2b = pk2(w2.z, w2.w);
        u64 w3a = pk2(w3.x, w3.y), w3b = pk2(w3.z, w3.w);
        NODE_STEP(v0, a00, a01);
        NODE_STEP(v1, a10, a11);
        NODE_STEP(v2, a20, a21);
        NODE_STEP(v3, a30, a31);
    }
#undef NODE_STEP

    {
        int ns[4] = {n0, n1, n2, n3};
        u64 lo[4] = {a00, a10, a20, a30};
        u64 hi[4] = {a01, a11, a21, a31};
#pragma unroll
        for (int j = 0; j < 4; j++) {
            int n = ns[j];
            if (n < NN) {
                float dv = g_dinv[n];
                float2 l = unpk2(lo[j]), h = unpk2(hi[j]);
                float4 r = make_float4(l.x * dv, l.y * dv, h.x * dv, h.y * dv);
                *(float4*)&g_h[n * NH + q * 4] = r;
            }
        }
    }
}

// GCN aggregate: h1[n] = dinv[n] * (sum_{in-edges} g_h[src] + g_h[n]) + b1
// one warp per node; 8 edge-slots x 4 lanes (each lane handles a c-quad)
__global__ void k_gcn(const float* __restrict__ b1) {
    int gw = (blockIdx.x * blockDim.x + threadIdx.x) >> 5;
    int lane = threadIdx.x & 31;
    if (gw >= NN) return;
    int n = gw;
    int start = g_rowstart[n];
    int end   = g_rowstart[n + 1];
    int grp = lane >> 2, q = lane & 3;

    float4 acc = make_float4(0.f, 0.f, 0.f, 0.f);
    for (int j = start + grp; j < end; j += 8) {
        int s = __ldg(&g_srcsorted[j]);
        float4 v = __ldg((const float4*)&g_h[s * NH + q * 4]);
        acc.x += v.x; acc.y += v.y; acc.z += v.z; acc.w += v.w;
    }
#pragma unroll
    for (int d = 4; d < 32; d <<= 1) {
        acc.x += __shfl_xor_sync(0xffffffffu, acc.x, d);
        acc.y += __shfl_xor_sync(0xffffffffu, acc.y, d);
        acc.z += __shfl_xor_sync(0xffffffffu, acc.z, d);
        acc.w += __shfl_xor_sync(0xffffffffu, acc.w, d);
    }
    if (lane < 4) {
        float4 self = *(const float4*)&g_h[n * NH + lane * 4];
        float dv = g_dinv[n];
        float4 bb = __ldg((const float4*)&b1[lane * 4]);
        float4 r;
        r.x = (acc.x + self.x) * dv + bb.x;
        r.y = (acc.y + self.y) * dv + bb.y;
        r.z = (acc.z + self.z) * dv + bb.z;
        r.w = (acc.w + self.w) * dv + bb.w;
        *(float4*)&g_h1[n * NH + lane * 4] = r;
    }
}

// SAGE: agg = mean_{in-edges} h1[src]; out = agg@Wl + h1[n]@Wr + b2; log_softmax
__global__ void k_sage(const float* __restrict__ Wl, const float* __restrict__ Wr,
                       const float* __restrict__ b2, float* __restrict__ out) {
    __shared__ float sWl[NH * NC], sWr[NH * NC], sB2[NC];
    __shared__ float sAgg[8][16], sH1[8][16];
    int t = threadIdx.x;
    for (int i = t; i < NH * NC; i += 256) { sWl[i] = Wl[i]; sWr[i] = Wr[i]; }
    if (t < NC) sB2[t] = b2[t];
    __syncthreads();

    int wib = t >> 5, lane = t & 31;
    int n = blockIdx.x * 8 + wib;
    if (n >= NN) return;

    int start = g_rowstart[n];
    int end   = g_rowstart[n + 1];
    int grp = lane >> 2, q = lane & 3;

    float4 acc = make_float4(0.f, 0.f, 0.f, 0.f);
    for (int j = start + grp; j < end; j += 8) {
        int s = __ldg(&g_srcsorted[j]);
        float4 v = __ldg((const float4*)&g_h1[s * NH + q * 4]);
        acc.x += v.x; acc.y += v.y; acc.z += v.z; acc.w += v.w;
    }
#pragma unroll
    for (int d = 4; d < 32; d <<= 1) {
        acc.x += __shfl_xor_sync(0xffffffffu, acc.x, d);
        acc.y += __shfl_xor_sync(0xffffffffu, acc.y, d);
        acc.z += __shfl_xor_sync(0xffffffffu, acc.z, d);
        acc.w += __shfl_xor_sync(0xffffffffu, acc.w, d);
    }
    float inv = 1.0f / fmaxf((float)(end - start), 1.0f);
    if (lane < 4) {
        float4 a;
        a.x = acc.x * inv; a.y = acc.y * inv; a.z = acc.z * inv; a.w = acc.w * inv;
        *(float4*)&sAgg[wib][lane * 4] = a;
        float4 h1v = *(const float4*)&g_h1[n * NH + lane * 4];
        *(float4*)&sH1[wib][lane * 4] = h1v;
    }
    __syncwarp();
    if (lane < 16) {
        float o = sB2[lane];
#pragma unroll
        for (int k = 0; k < 16; k++) {
            o += sAgg[wib][k] * sWl[k * NC + lane] + sH1[wib][k] * sWr[k * NC + lane];
        }
        float m = o;
#pragma unroll
        for (int d = 8; d >= 1; d >>= 1)
            m = fmaxf(m, __shfl_xor_sync(0xffffu, m, d));
        float e = __expf(o - m);
        float ssum = e;
#pragma unroll
        for (int d = 8; d >= 1; d >>= 1)
            ssum += __shfl_xor_sync(0xffffu, ssum, d);
        out[n * NC + lane] = (o - m) - __logf(ssum);
    }
}

// ---------------- launch ----------------
extern "C" void kernel_launch(void* const* d_in, const int* in_sizes, int n_in,
                              void* d_out, int out_size) {
    const float* x  = (const float*)d_in[0];
    const int*   ei = (const int*)d_in[1];
    const float* W1 = (const float*)d_in[2];
    const float* b1 = (const float*)d_in[3];
    const float* Wl = (const float*)d_in[4];
    const float* Wr = (const float*)d_in[5];
    const float* b2 = (const float*)d_in[6];
    float* out = (float*)d_out;

    const int* src = ei;
    const int* dst = ei + NE;

    void* cnt_ptr = nullptr;
    cudaGetSymbolAddress(&cnt_ptr, g_cnt);
    cudaMemsetAsync(cnt_ptr, 0, NN * sizeof(int), 0);

    k_count<<<(NE / 4) / 256, 256>>>(dst);
    k_scan_local<<<SCAN_BLOCKS, 256>>>();
    k_fixup<<<(NN + 255) / 256, 256>>>();
    k_scatter_gemm<<<GEMM_BLOCKS + SCATTER_BLOCKS, 256>>>(src, dst, x, W1);
    k_gcn<<<(NN * 32 + 255) / 256, 256>>>(b1);
    k_sage<<<(NN * 32 + 255) / 256, 256>>>(Wl, Wr, b2, out);
}

// round 6
// speedup vs baseline: 1.1963x; 1.0255x over previous
#include <cuda_runtime.h>
#include <cuda_bf16.h>
#include <math.h>

// Problem constants (fixed by the dataset)
#define NN 100000
#define NF 256
#define NH 16
#define NC 16
#define NE 3200000

#define SCAN_CHUNK 4096
#define SCAN_BLOCKS 25   // ceil(100000/4096)

typedef unsigned long long u64;

// ---------------- device scratch (static, allowed) ----------------
__device__ int   g_cnt[NN];            // in-degree (no self loop)
__device__ int   g_rowstart[NN + 1];   // CSR row offsets (by dst)
__device__ int   g_blocksums[SCAN_BLOCKS];
__device__ float g_dinv[NN];           // rsqrt(indeg+1)
__device__ float g_h[NN * NH];         // x@W1, then scaled by dinv in k_scale
__device__ float g_h1[NN * NH];        // GCN output
__device__ int   g_srcsorted[NE];      // src ids grouped by dst
__device__ int   g_rank[NE];           // per-edge rank within its dst bucket

// ---------------- f32x2 helpers (FFMA2 is PTX-only) ----------------
__device__ __forceinline__ u64 pk2(float a, float b) {
    u64 r; asm("mov.b64 %0, {%1, %2};" : "=l"(r) : "f"(a), "f"(b)); return r;
}
__device__ __forceinline__ u64 dup2(float a) {
    u64 r; asm("mov.b64 %0, {%1, %1};" : "=l"(r) : "f"(a)); return r;
}
__device__ __forceinline__ u64 ffma2(u64 a, u64 b, u64 c) {
    u64 d; asm("fma.rn.f32x2 %0, %1, %2, %3;" : "=l"(d) : "l"(a), "l"(b), "l"(c)); return d;
}
__device__ __forceinline__ float2 unpk2(u64 a) {
    float2 f; asm("mov.b64 {%0, %1}, %2;" : "=f"(f.x), "=f"(f.y) : "l"(a)); return f;
}

// ---------------- kernels ----------------

// histogram of dst + record each edge's rank within its bucket
__global__ void k_count(const int* __restrict__ dst) {
    int i = blockIdx.x * blockDim.x + threadIdx.x;   // i < NE/4
    int4 d = ((const int4*)dst)[i];
    int4 r;
    r.x = atomicAdd(&g_cnt[d.x], 1);
    r.y = atomicAdd(&g_cnt[d.y], 1);
    r.z = atomicAdd(&g_cnt[d.z], 1);
    r.w = atomicAdd(&g_cnt[d.w], 1);
    ((int4*)g_rank)[i] = r;
}

// per-block exclusive scan of g_cnt chunk -> g_rowstart (local), block total -> g_blocksums
__global__ void k_scan_local() {
    __shared__ int s[SCAN_CHUNK];
    __shared__ int tsum[256];
    int t = threadIdx.x;
    int base = blockIdx.x * SCAN_CHUNK;
    for (int i = t; i < SCAN_CHUNK; i += 256) {
        int idx = base + i;
        s[i] = (idx < NN) ? g_cnt[idx] : 0;
    }
    __syncthreads();

    int loc[16];
    int run = 0;
#pragma unroll
    for (int i = 0; i < 16; i++) {
        run += s[t * 16 + i];
        loc[i] = run;                 // inclusive within thread
    }
    tsum[t] = run;
    __syncthreads();
    for (int off = 1; off < 256; off <<= 1) {
        int v = (t >= off) ? tsum[t - off] : 0;
        __syncthreads();
        tsum[t] += v;
        __syncthreads();
    }
    int ex = (t == 0) ? 0 : tsum[t - 1];
#pragma unroll
    for (int i = 0; i < 16; i++) {
        s[t * 16 + i] = ex + (i ? loc[i - 1] : 0);   // exclusive per element
    }
    __syncthreads();
    for (int i = t; i < SCAN_CHUNK; i += 256) {
        int idx = base + i;
        if (idx < NN) g_rowstart[idx] = s[i];
    }
    if (t == 0) g_blocksums[blockIdx.x] = tsum[255];
}

// fixup: add scanned block sums (computed in smem here), init dinv
__global__ void k_fixup() {
    __shared__ int sbs[SCAN_BLOCKS];
    int t = threadIdx.x;
    if (t < SCAN_BLOCKS) sbs[t] = g_blocksums[t];
    __syncthreads();
    int i = blockIdx.x * 256 + t;
    if (i >= NN) return;
    int chunk = i >> 12;          // / SCAN_CHUNK
    int off = 0;
    for (int b = 0; b < chunk; b++) off += sbs[b];
    g_rowstart[i] += off;
    g_dinv[i] = rsqrtf((float)(g_cnt[i] + 1));
    if (i == 0) g_rowstart[NN] = NE;
}

// atomic-free CSR scatter: pos = rowstart[dst] + rank
__global__ void __launch_bounds__(256)
k_scatter(const int* __restrict__ src, const int* __restrict__ dst) {
    int i = blockIdx.x * 256 + threadIdx.x;   // i < NE/4
    int4 s = ((const int4*)src)[i];
    int4 d = ((const int4*)dst)[i];
    int4 r = ((const int4*)g_rank)[i];
    int p0 = __ldg(&g_rowstart[d.x]) + r.x;
    int p1 = __ldg(&g_rowstart[d.y]) + r.y;
    int p2 = __ldg(&g_rowstart[d.z]) + r.z;
    int p3 = __ldg(&g_rowstart[d.w]) + r.w;
    g_srcsorted[p0] = s.x;
    g_srcsorted[p1] = s.y;
    g_srcsorted[p2] = s.z;
    g_srcsorted[p3] = s.w;
}

// g_h[n,:] = x[n,:] @ W1   (UNscaled — no CSR dependency; 4 nodes/thread)
__global__ void __launch_bounds__(256)
k_gemm1(const float* __restrict__ x, const float* __restrict__ W1) {
    __shared__ float sW[NF * NH];   // 16 KB
    int t = threadIdx.x;
    for (int i = t; i < NF * NH; i += 256) sW[i] = W1[i];
    __syncthreads();

    int q = t & 3;
    int slot = t >> 2;                 // 0..63
    int base = blockIdx.x * 256;
    int n0 = base + slot;
    int n1 = n0 + 64, n2 = n0 + 128, n3 = n0 + 192;
    int c0 = min(n0, NN - 1), c1 = min(n1, NN - 1);
    int c2 = min(n2, NN - 1), c3 = min(n3, NN - 1);

    const float4* x0 = (const float4*)(x + (size_t)c0 * NF);
    const float4* x1 = (const float4*)(x + (size_t)c1 * NF);
    const float4* x2 = (const float4*)(x + (size_t)c2 * NF);
    const float4* x3 = (const float4*)(x + (size_t)c3 * NF);
    const float4* w4 = (const float4*)sW;   // w4[k*4 + q] = W1[k][4q..4q+3]

    u64 a00 = 0, a01 = 0, a10 = 0, a11 = 0, a20 = 0, a21 = 0, a30 = 0, a31 = 0;

#define NODE_STEP(V, A0, A1)                                        \
    do {                                                            \
        u64 dx = dup2((V).x), dy = dup2((V).y);                     \
        u64 dz = dup2((V).z), dw = dup2((V).w);                     \
        A0 = ffma2(dx, w0a, A0); A1 = ffma2(dx, w0b, A1);           \
        A0 = ffma2(dy, w1a, A0); A1 = ffma2(dy, w1b, A1);           \
        A0 = ffma2(dz, w2a, A0); A1 = ffma2(dz, w2b, A1);           \
        A0 = ffma2(dw, w3a, A0); A1 = ffma2(dw, w3b, A1);           \
    } while (0)

#pragma unroll 4
    for (int kk = 0; kk < 64; kk++) {
        float4 v0 = __ldcs(&x0[kk]);
        float4 v1 = __ldcs(&x1[kk]);
        float4 v2 = __ldcs(&x2[kk]);
        float4 v3 = __ldcs(&x3[kk]);
        int kb = kk * 16 + q;
        float4 w0 = w4[kb];
        float4 w1 = w4[kb + 4];
        float4 w2 = w4[kb + 8];
        float4 w3 = w4[kb + 12];
        u64 w0a = pk2(w0.x, w0.y), w0b = pk2(w0.z, w0.w);
        u64 w1a = pk2(w1.x, w1.y), w1b = pk2(w1.z, w1.w);
        u64 w2a = pk2(w2.x, w2.y), w2b = pk2(w2.z, w2.w);
        u64 w3a = pk2(w3.x, w3.y), w3b = pk2(w3.z, w3.w);
        NODE_STEP(v0, a00, a01);
        NODE_STEP(v1, a10, a11);
        NODE_STEP(v2, a20, a21);
        NODE_STEP(v3, a30, a31);
    }
#undef NODE_STEP

    {
        int ns[4] = {n0, n1, n2, n3};
        u64 lo[4] = {a00, a10, a20, a30};
        u64 hi[4] = {a01, a11, a21, a31};
#pragma unroll
        for (int j = 0; j < 4; j++) {
            int n = ns[j];
            if (n < NN) {
                float2 l = unpk2(lo[j]), h = unpk2(hi[j]);
                float4 r = make_float4(l.x, l.y, h.x, h.y);
                *(float4*)&g_h[n * NH + q * 4] = r;
            }
        }
    }
}

// g_h[n,:] *= dinv[n]   (tiny; depends on fixup + gemm only)
__global__ void k_scale() {
    int i = blockIdx.x * blockDim.x + threadIdx.x;   // i < NN*4
    if (i >= NN * 4) return;
    int n = i >> 2;
    float dv = g_dinv[n];
    float4 v = *(float4*)&g_h[i * 4];
    v.x *= dv; v.y *= dv; v.z *= dv; v.w *= dv;
    *(float4*)&g_h[i * 4] = v;
}

// GCN aggregate: h1[n] = dinv[n] * (sum_{in-edges} g_h[src] + g_h[n]) + b1
// one warp per node; 8 edge-slots x 4 lanes (each lane handles a c-quad)
__global__ void k_gcn(const float* __restrict__ b1) {
    int gw = (blockIdx.x * blockDim.x + threadIdx.x) >> 5;
    int lane = threadIdx.x & 31;
    if (gw >= NN) return;
    int n = gw;
    int start = g_rowstart[n];
    int end   = g_rowstart[n + 1];
    int grp = lane >> 2, q = lane & 3;

    float4 acc = make_float4(0.f, 0.f, 0.f, 0.f);
    for (int j = start + grp; j < end; j += 8) {
        int s = __ldg(&g_srcsorted[j]);
        float4 v = __ldg((const float4*)&g_h[s * NH + q * 4]);
        acc.x += v.x; acc.y += v.y; acc.z += v.z; acc.w += v.w;
    }
#pragma unroll
    for (int d = 4; d < 32; d <<= 1) {
        acc.x += __shfl_xor_sync(0xffffffffu, acc.x, d);
        acc.y += __shfl_xor_sync(0xffffffffu, acc.y, d);
        acc.z += __shfl_xor_sync(0xffffffffu, acc.z, d);
        acc.w += __shfl_xor_sync(0xffffffffu, acc.w, d);
    }
    if (lane < 4) {
        float4 self = *(const float4*)&g_h[n * NH + lane * 4];
        float dv = g_dinv[n];
        float4 bb = __ldg((const float4*)&b1[lane * 4]);
        float4 r;
        r.x = (acc.x + self.x) * dv + bb.x;
        r.y = (acc.y + self.y) * dv + bb.y;
        r.z = (acc.z + self.z) * dv + bb.z;
        r.w = (acc.w + self.w) * dv + bb.w;
        *(float4*)&g_h1[n * NH + lane * 4] = r;
    }
}

// SAGE: agg = mean_{in-edges} h1[src]; out = agg@Wl + h1[n]@Wr + b2; log_softmax
__global__ void k_sage(const float* __restrict__ Wl, const float* __restrict__ Wr,
                       const float* __restrict__ b2, float* __restrict__ out) {
    __shared__ float sWl[NH * NC], sWr[NH * NC], sB2[NC];
    __shared__ float sAgg[8][16], sH1[8][16];
    int t = threadIdx.x;
    for (int i = t; i < NH * NC; i += 256) { sWl[i] = Wl[i]; sWr[i] = Wr[i]; }
    if (t < NC) sB2[t] = b2[t];
    __syncthreads();

    int wib = t >> 5, lane = t & 31;
    int n = blockIdx.x * 8 + wib;
    if (n >= NN) return;

    int start = g_rowstart[n];
    int end   = g_rowstart[n + 1];
    int grp = lane >> 2, q = lane & 3;

    float4 acc = make_float4(0.f, 0.f, 0.f, 0.f);
    for (int j = start + grp; j < end; j += 8) {
        int s = __ldg(&g_srcsorted[j]);
        float4 v = __ldg((const float4*)&g_h1[s * NH + q * 4]);
        acc.x += v.x; acc.y += v.y; acc.z += v.z; acc.w += v.w;
    }
#pragma unroll
    for (int d = 4; d < 32; d <<= 1) {
        acc.x += __shfl_xor_sync(0xffffffffu, acc.x, d);
        acc.y += __shfl_xor_sync(0xffffffffu, acc.y, d);
        acc.z += __shfl_xor_sync(0xffffffffu, acc.z, d);
        acc.w += __shfl_xor_sync(0xffffffffu, acc.w, d);
    }
    float inv = 1.0f / fmaxf((float)(end - start), 1.0f);
    if (lane < 4) {
        float4 a;
        a.x = acc.x * inv; a.y = acc.y * inv; a.z = acc.z * inv; a.w = acc.w * inv;
        *(float4*)&sAgg[wib][lane * 4] = a;
        float4 h1v = *(const float4*)&g_h1[n * NH + lane * 4];
        *(float4*)&sH1[wib][lane * 4] = h1v;
    }
    __syncwarp();
    if (lane < 16) {
        float o = sB2[lane];
#pragma unroll
        for (int k = 0; k < 16; k++) {
            o += sAgg[wib][k] * sWl[k * NC + lane] + sH1[wib][k] * sWr[k * NC + lane];
        }
        float m = o;
#pragma unroll
        for (int d = 8; d >= 1; d >>= 1)
            m = fmaxf(m, __shfl_xor_sync(0xffffu, m, d));
        float e = __expf(o - m);
        float ssum = e;
#pragma unroll
        for (int d = 8; d >= 1; d >>= 1)
            ssum += __shfl_xor_sync(0xffffu, ssum, d);
        out[n * NC + lane] = (o - m) - __logf(ssum);
    }
}

// ---------------- launch (fork-join two-stream graph) ----------------
static cudaStream_t s2 = nullptr;
static cudaEvent_t evFork = nullptr, evFix = nullptr, evSide = nullptr;

extern "C" void kernel_launch(void* const* d_in, const int* in_sizes, int n_in,
                              void* d_out, int out_size) {
    const float* x  = (const float*)d_in[0];
    const int*   ei = (const int*)d_in[1];
    const float* W1 = (const float*)d_in[2];
    const float* b1 = (const float*)d_in[3];
    const float* Wl = (const float*)d_in[4];
    const float* Wr = (const float*)d_in[5];
    const float* b2 = (const float*)d_in[6];
    float* out = (float*)d_out;

    const int* src = ei;
    const int* dst = ei + NE;

    if (!s2) {
        cudaStreamCreateWithFlags(&s2, cudaStreamNonBlocking);
        cudaEventCreateWithFlags(&evFork, cudaEventDisableTiming);
        cudaEventCreateWithFlags(&evFix,  cudaEventDisableTiming);
        cudaEventCreateWithFlags(&evSide, cudaEventDisableTiming);
    }

    void* cnt_ptr = nullptr;
    cudaGetSymbolAddress(&cnt_ptr, g_cnt);

    // fork: side stream runs gemm (no CSR deps) concurrently with CSR build
    cudaEventRecord(evFork, 0);
    cudaStreamWaitEvent(s2, evFork, 0);
    k_gemm1<<<(NN + 255) / 256, 256, 0, s2>>>(x, W1);

    // main stream: CSR build
    cudaMemsetAsync(cnt_ptr, 0, NN * sizeof(int), 0);
    k_count<<<(NE / 4) / 256, 256>>>(dst);
    k_scan_local<<<SCAN_BLOCKS, 256>>>();
    k_fixup<<<(NN + 255) / 256, 256>>>();
    cudaEventRecord(evFix, 0);
    k_scatter<<<(NE / 4) / 256, 256>>>(src, dst);

    // side stream: scale g_h by dinv (needs fixup + gemm), overlaps scatter
    cudaStreamWaitEvent(s2, evFix, 0);
    k_scale<<<(NN * 4 + 255) / 256, 256, 0, s2>>>();
    cudaEventRecord(evSide, s2);

    // join, then aggregations
    cudaStreamWaitEvent(0, evSide, 0);
    k_gcn<<<(NN * 32 + 255) / 256, 256>>>(b1);
    k_sage<<<(NN * 32 + 255) / 256, 256>>>(Wl, Wr, b2, out);
}